// round 11
// baseline (speedup 1.0000x reference)
#include <cuda_runtime.h>

// ---------------------------------------------------------------------------
// ContrastiveCRFLoss — B200 (sm_100a), round 11.
//
// = round-8 (55.5us best) with the 5us prep launch eliminated:
//   - d_order statically initialized to IDENTITY; the spatial counting sort
//     runs as ONE extra block inside the sparse kernel (hides for free, per
//     R10 measurement) and is consumed by the NEXT call's gather. coords are
//     identical every call -> same permutation, same output, every call.
//   - gather loads use __ldcg (L2-only, sector-granular) to test/kill the
//     128B line-fill amplification seen on the __ldg path.
//   L1 fused_k : pairs(4) | sorted gather(3375) | zfill(4096)  (R8 order,
//                pairs moved to front to keep them off the tail)
//   L2 sps_k   : bid 0 = counting sort (R10-validated 256-thread version)
//                bids 1..4096 = sparse warp-per-pair (R8 verbatim)
//                + last-block reset of d_npairs/d_done (R10-validated)
// ---------------------------------------------------------------------------

#define NB    32
#define KC    27
#define NS    1000
#define HW    256
#define MAXP  32768
#define CD_MAX 105.0f

#define PAIRB 4
#define GB    3375
#define ZB    4096
#define NBLK  (PAIRB + GB + ZB)

// record table, transposed: d_recT[s][word][n], word 0..26=C, 27..29=G
__device__ float    d_recT[NS * 32 * NB];     // 4 MB
__device__ unsigned d_pairs[MAXP];            // (a<<10)|b
__device__ float    d_pcd[MAXP];
__device__ int      d_npairs;                 // reset by sps_k tail
__device__ int      d_done;

// identity-initialized sample order; rewritten (to the same sorted
// permutation) at the end of every call by sps_k's sort block.
#define C4(b)   (b), (b)+1, (b)+2, (b)+3
#define C16(b)  C4(b), C4((b)+4), C4((b)+8), C4((b)+12)
#define C64(b)  C16(b), C16((b)+16), C16((b)+32), C16((b)+48)
#define C256(b) C64(b), C64((b)+64), C64((b)+128), C64((b)+192)
__device__ int d_order[1024] = { C256(0), C256(256), C256(512), C256(768) };

// ---------------------------------------------------------------------------
// L1: pairs + sorted gather + zfill (contiguous roles, R8 structure)
// ---------------------------------------------------------------------------
__global__ void __launch_bounds__(256)
fused_k(const float* __restrict__ guidance,
        const float* __restrict__ clusters,
        const int*   __restrict__ coords,
        float4* __restrict__ out, int n4) {
    const int bid = blockIdx.x;
    const int tid = threadIdx.x;

    if (bid < PAIRB) {
        // ---- pair enumeration (R8 verbatim) ----
        int idx = bid * 256 + tid;
        // grid-stride over the 1M pair grid with only 4*256 threads? No —
        // keep R8's 1-thread-per-pair mapping via an inner loop (1024 iters).
        int a = idx;                               // row a in [0,1024)
        if (a < NS) {
            float arf = (float)__ldg(&coords[a]);
            float acf = (float)__ldg(&coords[NS + a]);
            for (int b = 0; b < NS; b++) {
                float dr = arf - (float)__ldg(&coords[b]);
                float dc = acf - (float)__ldg(&coords[NS + b]);
                float cd = dr * dr + dc * dc;
                if (cd <= CD_MAX) {
                    int pos = atomicAdd(&d_npairs, 1);
                    if (pos < MAXP) {
                        d_pairs[pos] = ((unsigned)a << 10) | (unsigned)b;
                        d_pcd[pos]   = cd;
                    }
                }
            }
        }
    } else if (bid < PAIRB + GB) {
        // ---- sorted gather (R8 verbatim, __ldcg loads) ----
        int idx = (bid - PAIRB) * 256 + tid;       // < 864000 exactly
        int nk   = idx / NS;                       // n*27 + k
        int sIdx = idx - nk * NS;
        int n = nk / KC;
        int k = nk - n * KC;

        int s = d_order[sIdx];
        int r = __ldg(&coords[s]);
        int c = __ldg(&coords[NS + s]);
        int px = r * HW + c;

        float v = __ldcg(&clusters[((size_t)nk * HW * HW) + px]);
        d_recT[((size_t)s * 32 + k) * NB + n] = v;

        if (k < 3) {
            float g = __ldcg(&guidance[(((size_t)n * 3 + k) * HW * HW) + px]);
            d_recT[((size_t)s * 32 + 27 + k) * NB + n] = g;
        }
    } else {
        // ---- zero-fill output (R8 verbatim) ----
        int zidx = (bid - PAIRB - GB) * 256 + tid; // [0, 1048576)
        float4 z = make_float4(0.f, 0.f, 0.f, 0.f);
        #pragma unroll
        for (int it = 0; it < 8; it++) {
            int i = zidx + it * (ZB * 256);
            if (i < n4) out[i] = z;
        }
    }
}

// ---------------------------------------------------------------------------
// L2: sparse compute (R8 verbatim) + sort block + counter reset
// ---------------------------------------------------------------------------
__global__ void __launch_bounds__(256)
sps_k(const int* __restrict__ coords, float* __restrict__ out) {
    const int bid = blockIdx.x;
    const int tid = threadIdx.x;

    if (bid == 0) {
        // ---- counting sort by spatial bin (px>>6) — R10-validated ----
        __shared__ int hist[1024];
        __shared__ int base[1024];
        __shared__ int wsum[8];
        __shared__ short sbin[NS];
        __shared__ short srank[NS];

        #pragma unroll
        for (int q = 0; q < 4; q++) hist[q * 256 + tid] = 0;
        __syncthreads();

        #pragma unroll
        for (int q = 0; q < 4; q++) {
            int i = q * 256 + tid;
            if (i < NS) {
                int r = __ldg(&coords[i]);
                int c = __ldg(&coords[NS + i]);
                int bin = (r * 256 + c) >> 6;
                sbin[i]  = (short)bin;
                srank[i] = (short)atomicAdd(&hist[bin], 1);
            }
        }
        __syncthreads();

        int h0 = hist[4 * tid + 0], h1 = hist[4 * tid + 1];
        int h2 = hist[4 * tid + 2], h3 = hist[4 * tid + 3];
        int tsum = h0 + h1 + h2 + h3;

        const int lane = tid & 31, w = tid >> 5;
        int v = tsum;
        #pragma unroll
        for (int o = 1; o < 32; o <<= 1) {
            int t = __shfl_up_sync(0xffffffffu, v, o);
            if (lane >= o) v += t;
        }
        if (lane == 31) wsum[w] = v;
        __syncthreads();
        if (tid < 8) {
            int s = wsum[tid];
            #pragma unroll
            for (int o = 1; o < 8; o <<= 1) {
                int t = __shfl_up_sync(0xffu, s, o);
                if (tid >= o) s += t;
            }
            wsum[tid] = s;
        }
        __syncthreads();
        int excl = ((w == 0) ? 0 : wsum[w - 1]) + v - tsum;
        base[4 * tid + 0] = excl;
        base[4 * tid + 1] = excl + h0;
        base[4 * tid + 2] = excl + h0 + h1;
        base[4 * tid + 3] = excl + h0 + h1 + h2;
        __syncthreads();

        #pragma unroll
        for (int q = 0; q < 4; q++) {
            int i = q * 256 + tid;
            if (i < NS)
                d_order[base[sbin[i]] + srank[i]] = i;
        }
    } else {
        // ---- sparse compute (R8 verbatim) ----
        int gw   = ((bid - 1) * 256 + tid) >> 5;
        int lane = tid & 31;

        int np = d_npairs;
        if (np > MAXP) np = MAXP;

        if (gw < np) {
            unsigned pr = d_pairs[gw];
            int a = (int)(pr >> 10);
            int b = (int)(pr & 1023u);
            float cd = d_pcd[gw];

            const float* ra = d_recT + (size_t)a * 32 * NB + lane;
            const float* rb = d_recT + (size_t)b * 32 * NB + lane;

            float dot = 0.f;
            #pragma unroll
            for (int k = 0; k < KC; k++)
                dot = fmaf(__ldg(ra + k * NB), __ldg(rb + k * NB), dot);

            float gd = 0.f;
            #pragma unroll
            for (int ch = 0; ch < 3; ch++) {
                float d = __ldg(ra + (27 + ch) * NB) - __ldg(rb + (27 + ch) * NB);
                gd = fmaf(d, d, gd);
            }

            float s1 = 10.0f * __expf(-cd - gd * 3.33333333f);
            float s2 = 3.0f  * __expf(-10.0f * cd);

            out[((size_t)lane * NS + a) * NS + b] = -dot * (s1 + s2);
        }
    }

    // ---- last-block reset of d_npairs/d_done (R10-validated pattern).
    // Every d_npairs read precedes its block's barrier; reset fires only
    // after ALL blocks arrive.
    __syncthreads();
    if (tid == 0) {
        int t = atomicAdd(&d_done, 1);
        if (t == (int)gridDim.x - 1) {
            d_npairs = 0;
            d_done   = 0;
        }
    }
}

// ---------------------------------------------------------------------------
extern "C" void kernel_launch(void* const* d_in, const int* in_sizes, int n_in,
                              void* d_out, int out_size) {
    const float* guidance = (const float*)d_in[0];
    const float* clusters = (const float*)d_in[1];
    const int*   coords   = (const int*)d_in[2];
    float* out = (float*)d_out;

    fused_k<<<NBLK, 256>>>(guidance, clusters, coords,
                           (float4*)out, out_size / 4);
    sps_k<<<1 + MAXP / 8, 256>>>(coords, out);
}

// round 12
// speedup vs baseline: 2.5760x; 2.5760x over previous
#include <cuda_runtime.h>

// ---------------------------------------------------------------------------
// ContrastiveCRFLoss — B200 (sm_100a), round 12.
//
// Base = round-8 (55.5us, best). Two isolated changes:
//   1. pair enumeration moved from fused_k into prep_k (4096 extra blocks,
//      hidden under the sort; d_npairs reset moved to sparse_k tail).
//   2. gather loads use plain LDG (not __ldg/RO path) to test the 128B
//      line-fill amplification hypothesis (measured ~105B per 4B access).
//
// L1 prep_k  : bid 0 = spatial counting sort (R10 256-thread version)
//              bid 1..4096 = pair enumeration (R8 verbatim)
// L2 fused_k : sorted gather (3375) | zfill (4096)   (R8 verbatim, plain LDG)
// L3 sparse_k: warp-per-pair, lane=batch (R8 verbatim) + last-block reset
//              of d_npairs/d_done (R10-validated).
//
// Exact-zero sparsity: out[n,a,b] != -0.0 only for integer pixel-dist^2
// cd <= 105 (~6k of 1M ordered pairs, batch independent).
// ---------------------------------------------------------------------------

#define NB    32
#define KC    27
#define NS    1000
#define HW    256
#define MAXP  32768
#define CD_MAX 105.0f

#define PB    4096                 // pair blocks (in prep launch)
#define GB    3375                 // gather blocks
#define ZB    4096                 // zfill blocks

// record table, transposed: d_recT[s][word][n], word 0..26=C, 27..29=G
__device__ float    d_recT[NS * 32 * NB];     // 4 MB
__device__ int      d_order[1024];            // sorted sample ids
__device__ unsigned d_pairs[MAXP];            // (a<<10)|b
__device__ float    d_pcd[MAXP];
__device__ int      d_npairs;                 // 0 at start (static init / sparse tail)
__device__ int      d_done;

// ---------------------------------------------------------------------------
// L1: sort (bid 0) + pair enumeration
// ---------------------------------------------------------------------------
__global__ void __launch_bounds__(256)
prep_k(const int* __restrict__ coords) {
    const int bid = blockIdx.x;
    const int tid = threadIdx.x;

    if (bid == 0) {
        // ---- counting sort by spatial bin (px >> 6) — R10-validated ----
        __shared__ int hist[1024];
        __shared__ int base[1024];
        __shared__ int wsum[8];
        __shared__ short sbin[NS];
        __shared__ short srank[NS];

        #pragma unroll
        for (int q = 0; q < 4; q++) hist[q * 256 + tid] = 0;
        __syncthreads();

        #pragma unroll
        for (int q = 0; q < 4; q++) {
            int i = q * 256 + tid;
            if (i < NS) {
                int r = __ldg(&coords[i]);
                int c = __ldg(&coords[NS + i]);
                int bin = (r * 256 + c) >> 6;              // 0..1023
                sbin[i]  = (short)bin;
                srank[i] = (short)atomicAdd(&hist[bin], 1);
            }
        }
        __syncthreads();

        int h0 = hist[4 * tid + 0], h1 = hist[4 * tid + 1];
        int h2 = hist[4 * tid + 2], h3 = hist[4 * tid + 3];
        int tsum = h0 + h1 + h2 + h3;

        const int lane = tid & 31, w = tid >> 5;
        int v = tsum;
        #pragma unroll
        for (int o = 1; o < 32; o <<= 1) {
            int t = __shfl_up_sync(0xffffffffu, v, o);
            if (lane >= o) v += t;                          // inclusive
        }
        if (lane == 31) wsum[w] = v;
        __syncthreads();
        if (tid < 8) {
            int s = wsum[tid];
            #pragma unroll
            for (int o = 1; o < 8; o <<= 1) {
                int t = __shfl_up_sync(0xffu, s, o);
                if (tid >= o) s += t;
            }
            wsum[tid] = s;
        }
        __syncthreads();
        int excl = ((w == 0) ? 0 : wsum[w - 1]) + v - tsum;
        base[4 * tid + 0] = excl;
        base[4 * tid + 1] = excl + h0;
        base[4 * tid + 2] = excl + h0 + h1;
        base[4 * tid + 3] = excl + h0 + h1 + h2;
        __syncthreads();

        #pragma unroll
        for (int q = 0; q < 4; q++) {
            int i = q * 256 + tid;
            if (i < NS)
                d_order[base[sbin[i]] + srank[i]] = i;
        }
    } else {
        // ---- pair enumeration (R8 verbatim mapping; d_npairs pre-reset) ----
        int idx = (bid - 1) * 256 + tid;                   // [0, 1048576)
        int a = idx >> 10;
        int b = idx & 1023;
        if (a < NS && b < NS) {
            float dr = (float)(__ldg(&coords[a])      - __ldg(&coords[b]));
            float dc = (float)(__ldg(&coords[NS + a]) - __ldg(&coords[NS + b]));
            float cd = dr * dr + dc * dc;
            if (cd <= CD_MAX) {
                int pos = atomicAdd(&d_npairs, 1);
                if (pos < MAXP) {
                    d_pairs[pos] = ((unsigned)a << 10) | (unsigned)b;
                    d_pcd[pos]   = cd;
                }
            }
        }
    }
}

// ---------------------------------------------------------------------------
// L2: sorted gather + zfill (R8 verbatim, gather uses PLAIN loads)
// ---------------------------------------------------------------------------
__global__ void __launch_bounds__(256)
fused_k(const float* __restrict__ guidance,
        const float* __restrict__ clusters,
        const int*   __restrict__ coords,
        float4* __restrict__ out, int n4) {
    const int bid = blockIdx.x;
    const int tid = threadIdx.x;

    if (bid < GB) {
        // ---- sorted gather ----
        int idx = bid * 256 + tid;                 // < 864000 exactly
        int nk   = idx / NS;                       // n*27 + k
        int sIdx = idx - nk * NS;
        int n = nk / KC;
        int k = nk - n * KC;

        int s = d_order[sIdx];
        int r = __ldg(&coords[s]);
        int c = __ldg(&coords[NS + s]);
        int px = r * HW + c;

        // plain LDG (sector-granular) — NOT the __ldg RO path
        float v = clusters[((size_t)nk * HW * HW) + px];
        d_recT[((size_t)s * 32 + k) * NB + n] = v;

        if (k < 3) {
            float g = guidance[(((size_t)n * 3 + k) * HW * HW) + px];
            d_recT[((size_t)s * 32 + 27 + k) * NB + n] = g;
        }
    } else {
        // ---- zero-fill output (R8 verbatim) ----
        int zidx = (bid - GB) * 256 + tid;         // [0, 1048576)
        float4 z = make_float4(0.f, 0.f, 0.f, 0.f);
        #pragma unroll
        for (int it = 0; it < 8; it++) {
            int i = zidx + it * (ZB * 256);
            if (i < n4) out[i] = z;
        }
    }
}

// ---------------------------------------------------------------------------
// L3: sparse compute (R8 verbatim) + last-block counter reset (R10 pattern)
// ---------------------------------------------------------------------------
__global__ void __launch_bounds__(256)
sparse_k(float* __restrict__ out) {
    int gw   = (blockIdx.x * blockDim.x + threadIdx.x) >> 5;
    int lane = threadIdx.x & 31;

    int np = d_npairs;
    if (np > MAXP) np = MAXP;

    if (gw < np) {
        unsigned pr = d_pairs[gw];
        int a = (int)(pr >> 10);
        int b = (int)(pr & 1023u);
        float cd = d_pcd[gw];

        const float* ra = d_recT + (size_t)a * 32 * NB + lane;
        const float* rb = d_recT + (size_t)b * 32 * NB + lane;

        float dot = 0.f;
        #pragma unroll
        for (int k = 0; k < KC; k++)
            dot = fmaf(__ldg(ra + k * NB), __ldg(rb + k * NB), dot);

        float gd = 0.f;
        #pragma unroll
        for (int ch = 0; ch < 3; ch++) {
            float d = __ldg(ra + (27 + ch) * NB) - __ldg(rb + (27 + ch) * NB);
            gd = fmaf(d, d, gd);
        }

        float s1 = 10.0f * __expf(-cd - gd * 3.33333333f);
        float s2 = 3.0f  * __expf(-10.0f * cd);

        out[((size_t)lane * NS + a) * NS + b] = -dot * (s1 + s2);
    }

    // ---- last-block reset of d_npairs/d_done for the next replay.
    // Every d_npairs read precedes its block's barrier; reset fires only
    // after ALL blocks have arrived (R10-validated).
    __syncthreads();
    if (threadIdx.x == 0) {
        int t = atomicAdd(&d_done, 1);
        if (t == (int)gridDim.x - 1) {
            d_npairs = 0;
            d_done   = 0;
        }
    }
}

// ---------------------------------------------------------------------------
extern "C" void kernel_launch(void* const* d_in, const int* in_sizes, int n_in,
                              void* d_out, int out_size) {
    const float* guidance = (const float*)d_in[0];
    const float* clusters = (const float*)d_in[1];
    const int*   coords   = (const int*)d_in[2];
    float* out = (float*)d_out;

    prep_k<<<1 + PB, 256>>>(coords);
    fused_k<<<GB + ZB, 256>>>(guidance, clusters, coords,
                              (float4*)out, out_size / 4);
    sparse_k<<<MAXP / 8, 256>>>(out);
}

// round 14
// speedup vs baseline: 2.6544x; 1.0304x over previous
#include <cuda_runtime.h>

// ---------------------------------------------------------------------------
// ContrastiveCRFLoss — B200 (sm_100a), round 14 (= R13 + spin hardening;
// R13 bench died at container acquisition, not in the kernel).
//
// 2-launch structure. Mega-kernel phases in block order:
//   bid 0            : spatial counting sort (R10-validated) -> fence -> flag
//   bid 1..1184      : zfill slice A (one occupancy wave; sort hides under it)
//   bid .. +3375     : sorted gather (R8 mapping; runs before the zfill flood;
//                      flag spin with __nanosleep is safety-only)
//   bid .. +2912     : zfill slice B
//   bid .. +4096     : pair enumeration (R8, atomic append; hidden in tail)
// sparse_k: R8 verbatim + last-block reset of d_npairs/d_done/d_flag.
//
// Exact-zero sparsity: out[n,a,b] != -0.0 only for integer pixel-dist^2
// cd <= 105 (~6k of 1M ordered pairs, batch independent).
// ---------------------------------------------------------------------------

#define NB    32
#define KC    27
#define NS    1000
#define HW    256
#define MAXP  32768
#define CD_MAX 105.0f

#define ZFA   1184                 // zfill slice A (one wave @ 8 CTA/SM x 148)
#define GB    3375                 // gather blocks
#define ZFB   2912                 // zfill slice B (ZFA+ZFB = 4096)
#define PB    4096                 // pair blocks
#define ZTOT  (ZFA + ZFB)          // 4096
#define NBLK  (1 + ZFA + GB + ZFB + PB)   // 11568

// record table, transposed: d_recT[s][word][n], word 0..26=C, 27..29=G
__device__ float    d_recT[NS * 32 * NB];     // 4 MB
__device__ int      d_order[1024];            // sorted sample ids
__device__ unsigned d_pairs[MAXP];            // (a<<10)|b
__device__ float    d_pcd[MAXP];
__device__ int      d_npairs;                 // static 0; reset by sparse tail
__device__ int      d_done;
__device__ int      d_flag;                   // sort-complete flag

// ---------------------------------------------------------------------------
// L1: mega-kernel
// ---------------------------------------------------------------------------
__global__ void __launch_bounds__(256)
mega_k(const float* __restrict__ guidance,
       const float* __restrict__ clusters,
       const int*   __restrict__ coords,
       float4* __restrict__ out, int n4) {
    const int bid = blockIdx.x;
    const int tid = threadIdx.x;

    if (bid == 0) {
        // ---- counting sort by spatial bin (px >> 6) — R10-validated ----
        __shared__ int hist[1024];
        __shared__ int base[1024];
        __shared__ int wsum[8];
        __shared__ short sbin[NS];
        __shared__ short srank[NS];

        #pragma unroll
        for (int q = 0; q < 4; q++) hist[q * 256 + tid] = 0;
        __syncthreads();

        #pragma unroll
        for (int q = 0; q < 4; q++) {
            int i = q * 256 + tid;
            if (i < NS) {
                int r = __ldg(&coords[i]);
                int c = __ldg(&coords[NS + i]);
                int bin = (r * 256 + c) >> 6;              // 0..1023
                sbin[i]  = (short)bin;
                srank[i] = (short)atomicAdd(&hist[bin], 1);
            }
        }
        __syncthreads();

        int h0 = hist[4 * tid + 0], h1 = hist[4 * tid + 1];
        int h2 = hist[4 * tid + 2], h3 = hist[4 * tid + 3];
        int tsum = h0 + h1 + h2 + h3;

        const int lane = tid & 31, w = tid >> 5;
        int v = tsum;
        #pragma unroll
        for (int o = 1; o < 32; o <<= 1) {
            int t = __shfl_up_sync(0xffffffffu, v, o);
            if (lane >= o) v += t;                          // inclusive
        }
        if (lane == 31) wsum[w] = v;
        __syncthreads();
        if (tid < 8) {
            int s = wsum[tid];
            #pragma unroll
            for (int o = 1; o < 8; o <<= 1) {
                int t = __shfl_up_sync(0xffu, s, o);
                if (tid >= o) s += t;
            }
            wsum[tid] = s;
        }
        __syncthreads();
        int excl = ((w == 0) ? 0 : wsum[w - 1]) + v - tsum;
        base[4 * tid + 0] = excl;
        base[4 * tid + 1] = excl + h0;
        base[4 * tid + 2] = excl + h0 + h1;
        base[4 * tid + 3] = excl + h0 + h1 + h2;
        __syncthreads();

        #pragma unroll
        for (int q = 0; q < 4; q++) {
            int i = q * 256 + tid;
            if (i < NS)
                d_order[base[sbin[i]] + srank[i]] = i;
        }
        __syncthreads();
        if (tid == 0) {
            __threadfence();
            atomicExch(&d_flag, 1);
        }
    } else if (bid <= ZFA || (bid > ZFA + GB && bid <= ZFA + GB + ZFB)) {
        // ---- zero-fill output (slices A and B share one ordinal space) ----
        int ord = (bid <= ZFA) ? (bid - 1) : (ZFA + bid - (ZFA + GB) - 1);
        int zidx = ord * 256 + tid;                // [0, 1048576)
        float4 z = make_float4(0.f, 0.f, 0.f, 0.f);
        #pragma unroll
        for (int it = 0; it < 8; it++) {
            int i = zidx + it * (ZTOT * 256);
            if (i < n4) out[i] = z;
        }
    } else if (bid <= ZFA + GB) {
        // ---- sorted gather (R8 mapping). Safety spin on sort flag:
        //      sort is bid 0 (wave 1, dispatched first), so this spin
        //      always terminates; nanosleep keeps the poll cooperative. ----
        if (tid == 0) {
            while (atomicAdd(&d_flag, 0) == 0) { __nanosleep(64); }
        }
        __syncthreads();

        int idx = (bid - ZFA - 1) * 256 + tid;     // < 864000 exactly
        int nk   = idx / NS;                       // n*27 + k
        int sIdx = idx - nk * NS;
        int n = nk / KC;
        int k = nk - n * KC;

        int s = __ldcg(&d_order[sIdx]);            // L2-coherent read
        int r = __ldg(&coords[s]);
        int c = __ldg(&coords[NS + s]);
        int px = r * HW + c;

        float v = clusters[((size_t)nk * HW * HW) + px];
        d_recT[((size_t)s * 32 + k) * NB + n] = v;

        if (k < 3) {
            float g = guidance[(((size_t)n * 3 + k) * HW * HW) + px];
            d_recT[((size_t)s * 32 + 27 + k) * NB + n] = g;
        }
    } else {
        // ---- pair enumeration (R8 verbatim; d_npairs pre-reset) ----
        int idx = (bid - 1 - ZFA - GB - ZFB) * 256 + tid;   // [0, 1048576)
        int a = idx >> 10;
        int b = idx & 1023;
        if (a < NS && b < NS) {
            float dr = (float)(__ldg(&coords[a])      - __ldg(&coords[b]));
            float dc = (float)(__ldg(&coords[NS + a]) - __ldg(&coords[NS + b]));
            float cd = dr * dr + dc * dc;
            if (cd <= CD_MAX) {
                int pos = atomicAdd(&d_npairs, 1);
                if (pos < MAXP) {
                    d_pairs[pos] = ((unsigned)a << 10) | (unsigned)b;
                    d_pcd[pos]   = cd;
                }
            }
        }
    }
}

// ---------------------------------------------------------------------------
// L2: sparse compute (R8 verbatim) + last-block counter reset (R10 pattern)
// ---------------------------------------------------------------------------
__global__ void __launch_bounds__(256)
sparse_k(float* __restrict__ out) {
    int gw   = (blockIdx.x * blockDim.x + threadIdx.x) >> 5;
    int lane = threadIdx.x & 31;

    int np = d_npairs;
    if (np > MAXP) np = MAXP;

    if (gw < np) {
        unsigned pr = d_pairs[gw];
        int a = (int)(pr >> 10);
        int b = (int)(pr & 1023u);
        float cd = d_pcd[gw];

        const float* ra = d_recT + (size_t)a * 32 * NB + lane;
        const float* rb = d_recT + (size_t)b * 32 * NB + lane;

        float dot = 0.f;
        #pragma unroll
        for (int k = 0; k < KC; k++)
            dot = fmaf(__ldg(ra + k * NB), __ldg(rb + k * NB), dot);

        float gd = 0.f;
        #pragma unroll
        for (int ch = 0; ch < 3; ch++) {
            float d = __ldg(ra + (27 + ch) * NB) - __ldg(rb + (27 + ch) * NB);
            gd = fmaf(d, d, gd);
        }

        float s1 = 10.0f * __expf(-cd - gd * 3.33333333f);
        float s2 = 3.0f  * __expf(-10.0f * cd);

        out[((size_t)lane * NS + a) * NS + b] = -dot * (s1 + s2);
    }

    // ---- last-block reset of d_npairs/d_done/d_flag for the next replay.
    // Every d_npairs read precedes its block's barrier; reset fires only
    // after ALL blocks have arrived (R10-validated).
    __syncthreads();
    if (threadIdx.x == 0) {
        int t = atomicAdd(&d_done, 1);
        if (t == (int)gridDim.x - 1) {
            d_npairs = 0;
            d_flag   = 0;
            d_done   = 0;
        }
    }
}

// ---------------------------------------------------------------------------
extern "C" void kernel_launch(void* const* d_in, const int* in_sizes, int n_in,
                              void* d_out, int out_size) {
    const float* guidance = (const float*)d_in[0];
    const float* clusters = (const float*)d_in[1];
    const int*   coords   = (const int*)d_in[2];
    float* out = (float*)d_out;

    mega_k<<<NBLK, 256>>>(guidance, clusters, coords,
                          (float4*)out, out_size / 4);
    sparse_k<<<MAXP / 8, 256>>>(out);
}

// round 15
// speedup vs baseline: 2.6759x; 1.0081x over previous
#include <cuda_runtime.h>

// ---------------------------------------------------------------------------
// ContrastiveCRFLoss — B200 (sm_100a), round 15.
//
// Base = R14 (55.7us; mega measured ~41.5 matching prediction). Two isolated
// changes targeting sparse_k's measured 11.1us (recT evicted from L2 by the
// 128MB zfill stream -> DRAM-latency-bound reads):
//   1. zfill stores use __stcs (evict-first) so the zero stream stops
//      evicting the 4MB recT table from L2.
//   2. sparse_k: one-wave grid (1184 blocks) + grid-stride over pairs +
//      __launch_bounds__(256,1) for reg headroom / load MLP.
//
// Mega-kernel phases in block order (R14 verbatim):
//   bid 0            : spatial counting sort -> fence -> flag
//   bid 1..1184      : zfill slice A (sort hides under it)
//   bid .. +3375     : sorted gather (flag spin is safety-only)
//   bid .. +2912     : zfill slice B
//   bid .. +4096     : pair enumeration (atomic append; hidden in tail)
// ---------------------------------------------------------------------------

#define NB    32
#define KC    27
#define NS    1000
#define HW    256
#define MAXP  32768
#define CD_MAX 105.0f

#define ZFA   1184
#define GB    3375
#define ZFB   2912
#define PB    4096
#define ZTOT  (ZFA + ZFB)
#define NBLK  (1 + ZFA + GB + ZFB + PB)

#define SPB   1184                 // sparse blocks: one occupancy wave

__device__ float    d_recT[NS * 32 * NB];     // 4 MB
__device__ int      d_order[1024];
__device__ unsigned d_pairs[MAXP];            // (a<<10)|b
__device__ float    d_pcd[MAXP];
__device__ int      d_npairs;                 // static 0; reset by sparse tail
__device__ int      d_done;
__device__ int      d_flag;

// ---------------------------------------------------------------------------
__global__ void __launch_bounds__(256)
mega_k(const float* __restrict__ guidance,
       const float* __restrict__ clusters,
       const int*   __restrict__ coords,
       float4* __restrict__ out, int n4) {
    const int bid = blockIdx.x;
    const int tid = threadIdx.x;

    if (bid == 0) {
        // ---- counting sort by spatial bin (px >> 6) ----
        __shared__ int hist[1024];
        __shared__ int base[1024];
        __shared__ int wsum[8];
        __shared__ short sbin[NS];
        __shared__ short srank[NS];

        #pragma unroll
        for (int q = 0; q < 4; q++) hist[q * 256 + tid] = 0;
        __syncthreads();

        #pragma unroll
        for (int q = 0; q < 4; q++) {
            int i = q * 256 + tid;
            if (i < NS) {
                int r = __ldg(&coords[i]);
                int c = __ldg(&coords[NS + i]);
                int bin = (r * 256 + c) >> 6;
                sbin[i]  = (short)bin;
                srank[i] = (short)atomicAdd(&hist[bin], 1);
            }
        }
        __syncthreads();

        int h0 = hist[4 * tid + 0], h1 = hist[4 * tid + 1];
        int h2 = hist[4 * tid + 2], h3 = hist[4 * tid + 3];
        int tsum = h0 + h1 + h2 + h3;

        const int lane = tid & 31, w = tid >> 5;
        int v = tsum;
        #pragma unroll
        for (int o = 1; o < 32; o <<= 1) {
            int t = __shfl_up_sync(0xffffffffu, v, o);
            if (lane >= o) v += t;
        }
        if (lane == 31) wsum[w] = v;
        __syncthreads();
        if (tid < 8) {
            int s = wsum[tid];
            #pragma unroll
            for (int o = 1; o < 8; o <<= 1) {
                int t = __shfl_up_sync(0xffu, s, o);
                if (tid >= o) s += t;
            }
            wsum[tid] = s;
        }
        __syncthreads();
        int excl = ((w == 0) ? 0 : wsum[w - 1]) + v - tsum;
        base[4 * tid + 0] = excl;
        base[4 * tid + 1] = excl + h0;
        base[4 * tid + 2] = excl + h0 + h1;
        base[4 * tid + 3] = excl + h0 + h1 + h2;
        __syncthreads();

        #pragma unroll
        for (int q = 0; q < 4; q++) {
            int i = q * 256 + tid;
            if (i < NS)
                d_order[base[sbin[i]] + srank[i]] = i;
        }
        __syncthreads();
        if (tid == 0) {
            __threadfence();
            atomicExch(&d_flag, 1);
        }
    } else if (bid <= ZFA || (bid > ZFA + GB && bid <= ZFA + GB + ZFB)) {
        // ---- zero-fill output: STREAMING stores (evict-first in L2) ----
        int ord = (bid <= ZFA) ? (bid - 1) : (ZFA + bid - (ZFA + GB) - 1);
        int zidx = ord * 256 + tid;
        float4 z = make_float4(0.f, 0.f, 0.f, 0.f);
        #pragma unroll
        for (int it = 0; it < 8; it++) {
            int i = zidx + it * (ZTOT * 256);
            if (i < n4) __stcs(&out[i], z);
        }
    } else if (bid <= ZFA + GB) {
        // ---- sorted gather (safety spin; sort is bid 0, always ahead) ----
        if (tid == 0) {
            while (atomicAdd(&d_flag, 0) == 0) { __nanosleep(64); }
        }
        __syncthreads();

        int idx = (bid - ZFA - 1) * 256 + tid;     // < 864000 exactly
        int nk   = idx / NS;
        int sIdx = idx - nk * NS;
        int n = nk / KC;
        int k = nk - n * KC;

        int s = __ldcg(&d_order[sIdx]);
        int r = __ldg(&coords[s]);
        int c = __ldg(&coords[NS + s]);
        int px = r * HW + c;

        float v = clusters[((size_t)nk * HW * HW) + px];
        d_recT[((size_t)s * 32 + k) * NB + n] = v;

        if (k < 3) {
            float g = guidance[(((size_t)n * 3 + k) * HW * HW) + px];
            d_recT[((size_t)s * 32 + 27 + k) * NB + n] = g;
        }
    } else {
        // ---- pair enumeration ----
        int idx = (bid - 1 - ZFA - GB - ZFB) * 256 + tid;
        int a = idx >> 10;
        int b = idx & 1023;
        if (a < NS && b < NS) {
            float dr = (float)(__ldg(&coords[a])      - __ldg(&coords[b]));
            float dc = (float)(__ldg(&coords[NS + a]) - __ldg(&coords[NS + b]));
            float cd = dr * dr + dc * dc;
            if (cd <= CD_MAX) {
                int pos = atomicAdd(&d_npairs, 1);
                if (pos < MAXP) {
                    d_pairs[pos] = ((unsigned)a << 10) | (unsigned)b;
                    d_pcd[pos]   = cd;
                }
            }
        }
    }
}

// ---------------------------------------------------------------------------
// L2: sparse compute — one-wave grid, grid-stride over pairs, reg headroom
// ---------------------------------------------------------------------------
__global__ void __launch_bounds__(256, 1)
sparse_k(float* __restrict__ out) {
    const int lane = threadIdx.x & 31;

    int np = d_npairs;
    if (np > MAXP) np = MAXP;

    const int W = (SPB * 256) >> 5;                         // total warps
    for (int gw = (blockIdx.x * blockDim.x + threadIdx.x) >> 5;
         gw < np; gw += W) {
        unsigned pr = d_pairs[gw];
        int a = (int)(pr >> 10);
        int b = (int)(pr & 1023u);
        float cd = d_pcd[gw];

        const float* ra = d_recT + (size_t)a * 32 * NB + lane;
        const float* rb = d_recT + (size_t)b * 32 * NB + lane;

        float dot = 0.f;
        #pragma unroll
        for (int k = 0; k < KC; k++)
            dot = fmaf(__ldg(ra + k * NB), __ldg(rb + k * NB), dot);

        float gd = 0.f;
        #pragma unroll
        for (int ch = 0; ch < 3; ch++) {
            float d = __ldg(ra + (27 + ch) * NB) - __ldg(rb + (27 + ch) * NB);
            gd = fmaf(d, d, gd);
        }

        float s1 = 10.0f * __expf(-cd - gd * 3.33333333f);
        float s2 = 3.0f  * __expf(-10.0f * cd);

        out[((size_t)lane * NS + a) * NS + b] = -dot * (s1 + s2);
    }

    // ---- last-block reset of d_npairs/d_done/d_flag for the next replay.
    // Every d_npairs read precedes its block's barrier; reset fires only
    // after ALL blocks have arrived (R10-validated).
    __syncthreads();
    if (threadIdx.x == 0) {
        int t = atomicAdd(&d_done, 1);
        if (t == (int)gridDim.x - 1) {
            d_npairs = 0;
            d_flag   = 0;
            d_done   = 0;
        }
    }
}

// ---------------------------------------------------------------------------
extern "C" void kernel_launch(void* const* d_in, const int* in_sizes, int n_in,
                              void* d_out, int out_size) {
    const float* guidance = (const float*)d_in[0];
    const float* clusters = (const float*)d_in[1];
    const int*   coords   = (const int*)d_in[2];
    float* out = (float*)d_out;

    mega_k<<<NBLK, 256>>>(guidance, clusters, coords,
                          (float4*)out, out_size / 4);
    sparse_k<<<SPB, 256>>>(out);
}

// round 16
// speedup vs baseline: 2.7639x; 1.0329x over previous
#include <cuda_runtime.h>

// ---------------------------------------------------------------------------
// ContrastiveCRFLoss — B200 (sm_100a), round 16.
//
// Changes vs R15 (55.3us):
//   1. mega phase order: sort | zfill | GATHER LAST | pairs — recT is the
//      most recently written 4MB in L2 with nothing after it to evict it,
//      so sparse_k reads warm L2 instead of row-thrashing DRAM (measured
//      10.3us, ~7MB from DRAM).
//   2. output symmetry (verified vs reference): out[n,a,b] == out[n,b,a]
//      exactly -> enumerate only b >= a (~3.5k pairs), write both cells.
//
// Mega phases in block order:
//   bid 0            : spatial counting sort -> fence -> flag
//   bid 1..4096      : zero-fill 128MB output (sort hides under wave 1)
//   bid .. +3375     : sorted gather (flag spin safety-only)
//   bid .. +4096     : pair enumeration, b >= a only (tail filler)
// sparse_k: one-wave grid-stride, warp per pair, lane = batch; writes the
//           (a,b) and (b,a) cells; last-block reset of counters.
// ---------------------------------------------------------------------------

#define NB    32
#define KC    27
#define NS    1000
#define HW    256
#define MAXP  32768
#define CD_MAX 105.0f

#define ZB    4096
#define GB    3375
#define PB    4096
#define NBLK  (1 + ZB + GB + PB)       // 11568
#define SPB   1184                     // sparse: one occupancy wave

__device__ float    d_recT[NS * 32 * NB];     // 4 MB  [s][word][n]
__device__ int      d_order[1024];
__device__ unsigned d_pairs[MAXP];            // (a<<10)|b,  b >= a
__device__ float    d_pcd[MAXP];
__device__ int      d_npairs;                 // static 0; reset by sparse tail
__device__ int      d_done;
__device__ int      d_flag;

// ---------------------------------------------------------------------------
__global__ void __launch_bounds__(256)
mega_k(const float* __restrict__ guidance,
       const float* __restrict__ clusters,
       const int*   __restrict__ coords,
       float4* __restrict__ out, int n4) {
    const int bid = blockIdx.x;
    const int tid = threadIdx.x;

    if (bid == 0) {
        // ---- counting sort by spatial bin (px >> 6) — R10-validated ----
        __shared__ int hist[1024];
        __shared__ int base[1024];
        __shared__ int wsum[8];
        __shared__ short sbin[NS];
        __shared__ short srank[NS];

        #pragma unroll
        for (int q = 0; q < 4; q++) hist[q * 256 + tid] = 0;
        __syncthreads();

        #pragma unroll
        for (int q = 0; q < 4; q++) {
            int i = q * 256 + tid;
            if (i < NS) {
                int r = __ldg(&coords[i]);
                int c = __ldg(&coords[NS + i]);
                int bin = (r * 256 + c) >> 6;
                sbin[i]  = (short)bin;
                srank[i] = (short)atomicAdd(&hist[bin], 1);
            }
        }
        __syncthreads();

        int h0 = hist[4 * tid + 0], h1 = hist[4 * tid + 1];
        int h2 = hist[4 * tid + 2], h3 = hist[4 * tid + 3];
        int tsum = h0 + h1 + h2 + h3;

        const int lane = tid & 31, w = tid >> 5;
        int v = tsum;
        #pragma unroll
        for (int o = 1; o < 32; o <<= 1) {
            int t = __shfl_up_sync(0xffffffffu, v, o);
            if (lane >= o) v += t;
        }
        if (lane == 31) wsum[w] = v;
        __syncthreads();
        if (tid < 8) {
            int s = wsum[tid];
            #pragma unroll
            for (int o = 1; o < 8; o <<= 1) {
                int t = __shfl_up_sync(0xffu, s, o);
                if (tid >= o) s += t;
            }
            wsum[tid] = s;
        }
        __syncthreads();
        int excl = ((w == 0) ? 0 : wsum[w - 1]) + v - tsum;
        base[4 * tid + 0] = excl;
        base[4 * tid + 1] = excl + h0;
        base[4 * tid + 2] = excl + h0 + h1;
        base[4 * tid + 3] = excl + h0 + h1 + h2;
        __syncthreads();

        #pragma unroll
        for (int q = 0; q < 4; q++) {
            int i = q * 256 + tid;
            if (i < NS)
                d_order[base[sbin[i]] + srank[i]] = i;
        }
        __syncthreads();
        if (tid == 0) {
            __threadfence();
            atomicExch(&d_flag, 1);
        }
    } else if (bid <= ZB) {
        // ---- zero-fill output ----
        int zidx = (bid - 1) * 256 + tid;              // [0, 1048576)
        float4 z = make_float4(0.f, 0.f, 0.f, 0.f);
        #pragma unroll
        for (int it = 0; it < 8; it++) {
            int i = zidx + it * (ZB * 256);
            if (i < n4) out[i] = z;
        }
    } else if (bid <= ZB + GB) {
        // ---- sorted gather, LAST heavy phase: recT stays warm in L2.
        //      Flag spin is safety-only (sort = bid 0, long retired). ----
        if (tid == 0) {
            while (atomicAdd(&d_flag, 0) == 0) { __nanosleep(64); }
        }
        __syncthreads();

        int idx = (bid - ZB - 1) * 256 + tid;          // < 864000 exactly
        int nk   = idx / NS;                           // n*27 + k
        int sIdx = idx - nk * NS;
        int n = nk / KC;
        int k = nk - n * KC;

        int s = __ldcg(&d_order[sIdx]);
        int r = __ldg(&coords[s]);
        int c = __ldg(&coords[NS + s]);
        int px = r * HW + c;

        float v = clusters[((size_t)nk * HW * HW) + px];
        d_recT[((size_t)s * 32 + k) * NB + n] = v;

        if (k < 3) {
            float g = guidance[(((size_t)n * 3 + k) * HW * HW) + px];
            d_recT[((size_t)s * 32 + 27 + k) * NB + n] = g;
        }
    } else {
        // ---- pair enumeration, b >= a only (symmetry) ----
        int idx = (bid - 1 - ZB - GB) * 256 + tid;     // [0, 1048576)
        int a = idx >> 10;
        int b = idx & 1023;
        if (a < NS && b < NS && b >= a) {
            float dr = (float)(__ldg(&coords[a])      - __ldg(&coords[b]));
            float dc = (float)(__ldg(&coords[NS + a]) - __ldg(&coords[NS + b]));
            float cd = dr * dr + dc * dc;
            if (cd <= CD_MAX) {
                int pos = atomicAdd(&d_npairs, 1);
                if (pos < MAXP) {
                    d_pairs[pos] = ((unsigned)a << 10) | (unsigned)b;
                    d_pcd[pos]   = cd;
                }
            }
        }
    }
}

// ---------------------------------------------------------------------------
// L2: sparse compute — warp per pair (b >= a), writes BOTH symmetric cells
// ---------------------------------------------------------------------------
__global__ void __launch_bounds__(256, 1)
sparse_k(float* __restrict__ out) {
    const int lane = threadIdx.x & 31;

    int np = d_npairs;
    if (np > MAXP) np = MAXP;

    const int W = (SPB * 256) >> 5;
    for (int gw = (blockIdx.x * blockDim.x + threadIdx.x) >> 5;
         gw < np; gw += W) {
        unsigned pr = d_pairs[gw];
        int a = (int)(pr >> 10);
        int b = (int)(pr & 1023u);
        float cd = d_pcd[gw];

        const float* ra = d_recT + (size_t)a * 32 * NB + lane;
        const float* rb = d_recT + (size_t)b * 32 * NB + lane;

        float dot = 0.f;
        #pragma unroll
        for (int k = 0; k < KC; k++)
            dot = fmaf(__ldg(ra + k * NB), __ldg(rb + k * NB), dot);

        float gd = 0.f;
        #pragma unroll
        for (int ch = 0; ch < 3; ch++) {
            float d = __ldg(ra + (27 + ch) * NB) - __ldg(rb + (27 + ch) * NB);
            gd = fmaf(d, d, gd);
        }

        float s1 = 10.0f * __expf(-cd - gd * 3.33333333f);
        float s2 = 3.0f  * __expf(-10.0f * cd);
        float val = -dot * (s1 + s2);

        size_t planeBase = (size_t)lane * NS * NS;
        out[planeBase + (size_t)a * NS + b] = val;
        if (b != a)
            out[planeBase + (size_t)b * NS + a] = val;   // exact symmetry
    }

    // ---- last-block reset of d_npairs/d_done/d_flag for the next replay.
    // Every d_npairs read precedes its block's barrier; reset fires only
    // after ALL blocks have arrived (R10-validated).
    __syncthreads();
    if (threadIdx.x == 0) {
        int t = atomicAdd(&d_done, 1);
        if (t == (int)gridDim.x - 1) {
            d_npairs = 0;
            d_flag   = 0;
            d_done   = 0;
        }
    }
}

// ---------------------------------------------------------------------------
extern "C" void kernel_launch(void* const* d_in, const int* in_sizes, int n_in,
                              void* d_out, int out_size) {
    const float* guidance = (const float*)d_in[0];
    const float* clusters = (const float*)d_in[1];
    const int*   coords   = (const int*)d_in[2];
    float* out = (float*)d_out;

    mega_k<<<NBLK, 256>>>(guidance, clusters, coords,
                          (float4*)out, out_size / 4);
    sparse_k<<<SPB, 256>>>(out);
}